// round 8
// baseline (speedup 1.0000x reference)
#include <cuda_runtime.h>
#include <cuda_bf16.h>
#include <math.h>
#include <stdint.h>
#include <string.h>

#define NH   16
#define DHD  64
#define NB   4
#define LQ   1024
#define LK   2048
#define DM   1024
#define MAXPOS 2048
#define STR  72    // bf16 smem row stride (144B)
#define SSTR 136   // S23 bf16 stride

// ---------------- static device scratch ----------------
__device__ __nv_bfloat16 g_Qh[(size_t)NB*NH*LQ*DHD];
__device__ __nv_bfloat16 g_Ql[(size_t)NB*NH*LQ*DHD];
__device__ __nv_bfloat16 g_Kh[(size_t)NB*NH*LK*DHD];
__device__ __nv_bfloat16 g_Kl[(size_t)NB*NH*LK*DHD];
__device__ __nv_bfloat16 g_VtH[(size_t)NB*NH*DHD*LK];  // [b,h][d][r]
__device__ __nv_bfloat16 g_VtL[(size_t)NB*NH*DHD*LK];
__device__ __nv_bfloat16 g_EbH[(size_t)(2*MAXPOS-1)*DHD];

__device__ __nv_bfloat16 g_Xqh[(size_t)NB*LQ*DM];
__device__ __nv_bfloat16 g_Xql[(size_t)NB*LQ*DM];
__device__ __nv_bfloat16 g_Xkh[(size_t)NB*LK*DM];
__device__ __nv_bfloat16 g_Xkl[(size_t)NB*LK*DM];
__device__ __nv_bfloat16 g_Wh[3][(size_t)DM*DM];
__device__ __nv_bfloat16 g_Wl[3][(size_t)DM*DM];

// ============================ helpers ============================
__device__ __forceinline__ uint32_t smem_u32(const void* p) {
    uint32_t a;
    asm("{ .reg .u64 t; cvta.to.shared.u64 t, %1; cvt.u32.u64 %0, t; }"
        : "=r"(a) : "l"(p));
    return a;
}
__device__ __forceinline__ void cp_async16(uint32_t saddr, const void* gaddr) {
    asm volatile("cp.async.cg.shared.global [%0], [%1], 16;" :: "r"(saddr), "l"(gaddr));
}
__device__ __forceinline__ void cp_commit() { asm volatile("cp.async.commit_group;"); }
template <int N>
__device__ __forceinline__ void cp_wait() { asm volatile("cp.async.wait_group %0;" :: "n"(N)); }

__device__ __forceinline__ void mma_bf16(float* c, const uint32_t* a, const uint32_t* b) {
    asm volatile(
        "mma.sync.aligned.m16n8k16.row.col.f32.bf16.bf16.f32 "
        "{%0,%1,%2,%3}, {%4,%5,%6,%7}, {%8,%9}, {%0,%1,%2,%3};"
        : "+f"(c[0]), "+f"(c[1]), "+f"(c[2]), "+f"(c[3])
        : "r"(a[0]), "r"(a[1]), "r"(a[2]), "r"(a[3]), "r"(b[0]), "r"(b[1]));
}
__device__ __forceinline__ uint32_t bfpack(float x, float y) {
    __nv_bfloat162 h(__float2bfloat16(x), __float2bfloat16(y));
    uint32_t u; memcpy(&u, &h, 4); return u;
}
__device__ __forceinline__ void bfsplit(float x, float y, uint32_t& hi, uint32_t& lo) {
    __nv_bfloat16 hx = __float2bfloat16(x), hy = __float2bfloat16(y);
    __nv_bfloat162 h2(hx, hy); memcpy(&hi, &h2, 4);
    __nv_bfloat162 l2(__float2bfloat16(x - __bfloat162float(hx)),
                      __float2bfloat16(y - __bfloat162float(hy)));
    memcpy(&lo, &l2, 4);
}

// =================================================================================
__global__ void split_kernel(const float* __restrict__ x,
                             __nv_bfloat16* __restrict__ hi,
                             __nv_bfloat16* __restrict__ lo, int n4)
{
    int i = blockIdx.x * blockDim.x + threadIdx.x;
    if (i >= n4) return;
    float4 v = ((const float4*)x)[i];
    uint32_t h0, l0, h1, l1;
    bfsplit(v.x, v.y, h0, l0);
    bfsplit(v.z, v.w, h1, l1);
    ((uint32_t*)hi)[2*i] = h0; ((uint32_t*)hi)[2*i+1] = h1;
    ((uint32_t*)lo)[2*i] = l0; ((uint32_t*)lo)[2*i+1] = l1;
}
__global__ void conv_kernel(const float* __restrict__ x,
                            __nv_bfloat16* __restrict__ y, int n4)
{
    int i = blockIdx.x * blockDim.x + threadIdx.x;
    if (i >= n4) return;
    float4 v = ((const float4*)x)[i];
    ((uint32_t*)y)[2*i]   = bfpack(v.x, v.y);
    ((uint32_t*)y)[2*i+1] = bfpack(v.z, v.w);
}

// =================================================================================
// Projection GEMM (proven); epilogue emits bf16 hi/lo. mode 0: [B,H,L,64]; mode 1: V^T
// =================================================================================
#define BK      32
#define KS_STR  40
#define TILE_BF (128 * KS_STR)
#define STAGE_BF (4 * TILE_BF)
#define PROJ_SMEM_BYTES (2 * STAGE_BF * 2)

__global__ __launch_bounds__(256, 1)
void proj_tc(const __nv_bfloat16* __restrict__ Ah_g, const __nv_bfloat16* __restrict__ Al_g,
             const __nv_bfloat16* __restrict__ Bh_g, const __nv_bfloat16* __restrict__ Bl_g,
             const float* __restrict__ bias,
             __nv_bfloat16* __restrict__ outH, __nv_bfloat16* __restrict__ outL,
             int L, int mode)
{
    extern __shared__ __nv_bfloat16 smem[];
    const uint32_t smem_b = smem_u32(smem);
    const int t = threadIdx.x, lane = t & 31;
    const int wid = t >> 5, g = lane >> 2, t4 = lane & 3;
    const int wm0 = (wid & 3) * 32, wn0 = (wid >> 2) * 64;
    const int m0 = blockIdx.x * 128, n0 = blockIdx.y * 128;
    const int c0 = t * 2;
    const int row0 = c0 >> 2, seg0 = c0 & 3;
    const int row1 = (c0 + 1) >> 2, seg1 = (c0 + 1) & 3;
    const int NS = DM / BK;

    auto load_stage = [&](int kc) {
        const int k0 = kc * BK;
        const uint32_t sb = smem_b + (uint32_t)(kc & 1) * STAGE_BF * 2;
        const uint32_t so0 = (uint32_t)(row0 * KS_STR + seg0 * 8) * 2;
        const uint32_t so1 = (uint32_t)(row1 * KS_STR + seg1 * 8) * 2;
        const size_t ga0 = (size_t)(m0 + row0) * DM + k0 + seg0 * 8;
        const size_t ga1 = (size_t)(m0 + row1) * DM + k0 + seg1 * 8;
        const size_t gb0 = (size_t)(n0 + row0) * DM + k0 + seg0 * 8;
        const size_t gb1 = (size_t)(n0 + row1) * DM + k0 + seg1 * 8;
        cp_async16(sb + 0 * TILE_BF * 2 + so0, Ah_g + ga0);
        cp_async16(sb + 0 * TILE_BF * 2 + so1, Ah_g + ga1);
        cp_async16(sb + 1 * TILE_BF * 2 + so0, Al_g + ga0);
        cp_async16(sb + 1 * TILE_BF * 2 + so1, Al_g + ga1);
        cp_async16(sb + 2 * TILE_BF * 2 + so0, Bh_g + gb0);
        cp_async16(sb + 2 * TILE_BF * 2 + so1, Bh_g + gb1);
        cp_async16(sb + 3 * TILE_BF * 2 + so0, Bl_g + gb0);
        cp_async16(sb + 3 * TILE_BF * 2 + so1, Bl_g + gb1);
        cp_commit();
    };

    float acc[2][8][4];
#pragma unroll
    for (int i = 0; i < 2; i++)
#pragma unroll
        for (int j = 0; j < 8; j++)
#pragma unroll
            for (int q = 0; q < 4; q++) acc[i][j][q] = 0.0f;

    load_stage(0);
    for (int kc = 0; kc < NS; kc++) {
        if (kc + 1 < NS) { load_stage(kc + 1); cp_wait<1>(); }
        else             { cp_wait<0>(); }
        __syncthreads();
        const __nv_bfloat16* sAh = smem + (size_t)(kc & 1) * STAGE_BF;
        const __nv_bfloat16* sAl = sAh + TILE_BF;
        const __nv_bfloat16* sBh = sAl + TILE_BF;
        const __nv_bfloat16* sBl = sBh + TILE_BF;
#pragma unroll
        for (int ks = 0; ks < BK; ks += 16) {
            uint32_t aH[2][4], aL[2][4], bH[8][2], bL[8][2];
            const int kk = ks + t4 * 2;
#pragma unroll
            for (int i = 0; i < 2; i++) {
                const int r = wm0 + i * 16 + g;
                aH[i][0] = *(const uint32_t*)&sAh[r * KS_STR + kk];
                aH[i][1] = *(const uint32_t*)&sAh[(r + 8) * KS_STR + kk];
                aH[i][2] = *(const uint32_t*)&sAh[r * KS_STR + kk + 8];
                aH[i][3] = *(const uint32_t*)&sAh[(r + 8) * KS_STR + kk + 8];
                aL[i][0] = *(const uint32_t*)&sAl[r * KS_STR + kk];
                aL[i][1] = *(const uint32_t*)&sAl[(r + 8) * KS_STR + kk];
                aL[i][2] = *(const uint32_t*)&sAl[r * KS_STR + kk + 8];
                aL[i][3] = *(const uint32_t*)&sAl[(r + 8) * KS_STR + kk + 8];
            }
#pragma unroll
            for (int j = 0; j < 8; j++) {
                const int n = wn0 + j * 8 + g;
                bH[j][0] = *(const uint32_t*)&sBh[n * KS_STR + kk];
                bH[j][1] = *(const uint32_t*)&sBh[n * KS_STR + kk + 8];
                bL[j][0] = *(const uint32_t*)&sBl[n * KS_STR + kk];
                bL[j][1] = *(const uint32_t*)&sBl[n * KS_STR + kk + 8];
            }
#pragma unroll
            for (int i = 0; i < 2; i++)
#pragma unroll
                for (int j = 0; j < 8; j++) {
                    mma_bf16(acc[i][j], aH[i], bH[j]);
                    mma_bf16(acc[i][j], aH[i], bL[j]);
                    mma_bf16(acc[i][j], aL[i], bH[j]);
                }
        }
        __syncthreads();
    }
#pragma unroll
    for (int i = 0; i < 2; i++)
#pragma unroll
        for (int j = 0; j < 8; j++) {
            const int cc = n0 + wn0 + j * 8 + t4 * 2;
            const int hh = cc >> 6, dh = cc & 63;
            const float b0 = __ldg(&bias[cc]), b1 = __ldg(&bias[cc + 1]);
#pragma unroll
            for (int rr = 0; rr < 2; rr++) {
                const int r = m0 + wm0 + i * 16 + g + rr * 8;
                const int bidx = r / L, l = r - bidx * L;
                const float f0 = acc[i][j][rr * 2 + 0] + b0;
                const float f1 = acc[i][j][rr * 2 + 1] + b1;
                __nv_bfloat16 h0 = __float2bfloat16(f0);
                __nv_bfloat16 h1 = __float2bfloat16(f1);
                __nv_bfloat16 e0 = __float2bfloat16(f0 - __bfloat162float(h0));
                __nv_bfloat16 e1 = __float2bfloat16(f1 - __bfloat162float(h1));
                if (mode == 0) {
                    const size_t base = ((size_t)(bidx * NH + hh) * L + l) * DHD + dh;
                    *(__nv_bfloat162*)&outH[base] = __nv_bfloat162(h0, h1);
                    *(__nv_bfloat162*)&outL[base] = __nv_bfloat162(e0, e1);
                } else {
                    const size_t base = ((size_t)(bidx * NH + hh) * DHD + dh) * LK + l;
                    outH[base] = h0; outH[base + LK] = h1;
                    outL[base] = e0; outL[base + LK] = e1;
                }
            }
        }
}

// =================================================================================
// Tensor-core attention: 512 threads, banded GEMM1, 3-term PV, double-buffered loads
// =================================================================================
#define OFF_KH  0
#define OFF_KL  9216
#define OFF_VTH 18432
#define OFF_VTL 27648
#define OFF_ES  36864
#define OFF_MS  55296
#define BUF_BYTES 55552

#define SM_S23 0
#define SM_SL  34816
#define SM_QH  52224
#define SM_QL  61440
#define SM_BUF 70656
#define SM_PH  181760
#define SM_PL  190976
#define SM_MR  200192
#define SM_LS  200448
#define SM_CS  200704
#define ATTN_SMEM 200960

__global__ __launch_bounds__(512, 1)
void attn_tc(const float* __restrict__ mask, float* __restrict__ out)
{
    extern __shared__ char smc[];
    const uint32_t sbu = smem_u32(smc);
    __nv_bfloat16* S23 = (__nv_bfloat16*)(smc + SM_S23);   // [128][SSTR]
    float* Sl = (float*)(smc + SM_SL);                      // [64][68]
    __nv_bfloat16* Qh = (__nv_bfloat16*)(smc + SM_QH);
    __nv_bfloat16* Ql = (__nv_bfloat16*)(smc + SM_QL);
    __nv_bfloat16* Ph = (__nv_bfloat16*)(smc + SM_PH);
    __nv_bfloat16* Pl = (__nv_bfloat16*)(smc + SM_PL);
    float* Mr = (float*)(smc + SM_MR);
    float* Ls = (float*)(smc + SM_LS);
    float* Cs = (float*)(smc + SM_CS);

    const int t = threadIdx.x, lane = t & 31, w = t >> 5;   // 16 warps
    const int g = lane >> 2, t4 = lane & 3;
    const int sm0 = (w & 3) * 16, sn0 = (w >> 2) * 16;      // QK/PV: 4m x 4n of 16x16
    const int l0 = blockIdx.x * 64, hd = blockIdx.y, b = blockIdx.z;

    const __nv_bfloat16* Qhg = g_Qh + ((size_t)(b * NH + hd) * LQ + l0) * DHD;
    const __nv_bfloat16* Qlg = g_Ql + ((size_t)(b * NH + hd) * LQ + l0) * DHD;
    const __nv_bfloat16* Khg = g_Kh + (size_t)(b * NH + hd) * LK * DHD;
    const __nv_bfloat16* Klg = g_Kl + (size_t)(b * NH + hd) * LK * DHD;
    const __nv_bfloat16* Vhg = g_VtH + (size_t)(b * NH + hd) * DHD * LK;
    const __nv_bfloat16* Vlg = g_VtL + (size_t)(b * NH + hd) * DHD * LK;
    const float* mg = mask + (size_t)b * LK;

    // initial loads: Q + first buffer (one cp group)
    {
        const int row = t >> 3, c = t & 7;
        cp_async16(sbu + SM_QH + row * 144 + c * 16, Qhg + row * DHD + c * 8);
        cp_async16(sbu + SM_QL + row * 144 + c * 16, Qlg + row * DHD + c * 8);
        cp_async16(sbu + SM_BUF + OFF_KH + row * 144 + c * 16, Khg + (size_t)row * DHD + c * 8);
        cp_async16(sbu + SM_BUF + OFF_KL + row * 144 + c * 16, Klg + (size_t)row * DHD + c * 8);
        cp_async16(sbu + SM_BUF + OFF_VTH + row * 144 + c * 16, Vhg + (size_t)row * LK + c * 8);
        cp_async16(sbu + SM_BUF + OFF_VTL + row * 144 + c * 16, Vlg + (size_t)row * LK + c * 8);
        const int eb0 = l0 + (MAXPOS - 64);
#pragma unroll
        for (int i = 0; i < 2; i++) {
            int q = t + 512 * i;
            if (q < 127 * 8) {
                int rw = q >> 3, cc = q & 7;
                cp_async16(sbu + SM_BUF + OFF_ES + rw * 144 + cc * 16,
                           g_EbH + (size_t)(eb0 + rw) * DHD + cc * 8);
            }
        }
        if (t < 16) cp_async16(sbu + SM_BUF + OFF_MS + t * 16, mg + t * 4);
        cp_commit();
    }

    if (t < 64) { Mr[t] = -1e30f; Ls[t] = 0.f; }
    if (t < 72) {  // zero Es row 127 in both buffers
        int bb = t / 36, wd = t % 36;
        *(uint32_t*)(smc + SM_BUF + bb * BUF_BYTES + OFF_ES + 127 * 144 + wd * 4) = 0u;
    }

    float O[2][4];
#pragma unroll
    for (int j = 0; j < 2; j++)
#pragma unroll
        for (int q = 0; q < 4; q++) O[j][q] = 0.f;

    // GEMM1 banding per warp: 16-row m-blocks, 80-wide diagonal band (10 n-tiles, 5/warp-half)
    const int rb16 = w >> 1;
    int arow0, band0, drow0;
    bool isQ = (rb16 < 4);
    if (isQ) { arow0 = rb16 * 16; band0 = rb16 * 16; drow0 = rb16 * 16; }
    else     { int rk = (rb16 - 4) * 16; arow0 = rk; band0 = 48 - rk; drow0 = 64 + rk; }
    const int nt0 = band0 / 8 + (w & 1) * 5;

    for (int kt = 0; kt < LK / 64; kt++) {
        const int bb = kt & 1;
        const char* B = smc + SM_BUF + bb * BUF_BYTES;
        cp_wait<0>();
        __syncthreads();

        if (kt + 1 < LK / 64) {  // prefetch next tiles
            const int r1 = (kt + 1) * 64;
            const uint32_t P = sbu + SM_BUF + (bb ^ 1) * BUF_BYTES;
            const int row = t >> 3, c = t & 7;
            cp_async16(P + OFF_KH + row * 144 + c * 16, Khg + (size_t)(r1 + row) * DHD + c * 8);
            cp_async16(P + OFF_KL + row * 144 + c * 16, Klg + (size_t)(r1 + row) * DHD + c * 8);
            cp_async16(P + OFF_VTH + row * 144 + c * 16, Vhg + (size_t)row * LK + r1 + c * 8);
            cp_async16(P + OFF_VTL + row * 144 + c * 16, Vlg + (size_t)row * LK + r1 + c * 8);
            const int eb1 = l0 - r1 + (MAXPOS - 64);
#pragma unroll
            for (int i = 0; i < 2; i++) {
                int q = t + 512 * i;
                if (q < 127 * 8) {
                    int rw = q >> 3, cc = q & 7;
                    cp_async16(P + OFF_ES + rw * 144 + cc * 16,
                               g_EbH + (size_t)(eb1 + rw) * DHD + cc * 8);
                }
            }
            if (t < 16) cp_async16(P + OFF_MS + t * 16, mg + r1 + t * 4);
            cp_commit();
        }

        const __nv_bfloat16* KhS = (const __nv_bfloat16*)(B + OFF_KH);
        const __nv_bfloat16* KlS = (const __nv_bfloat16*)(B + OFF_KL);
        const __nv_bfloat16* VhS = (const __nv_bfloat16*)(B + OFF_VTH);
        const __nv_bfloat16* VlS = (const __nv_bfloat16*)(B + OFF_VTL);
        const __nv_bfloat16* EsS = (const __nv_bfloat16*)(B + OFF_ES);
        const float* MsS = (const float*)(B + OFF_MS);

        // ---- GEMM1 (banded): S23 = [Qh;Kh] @ Es^T ----
        {
            const __nv_bfloat16* Ab = isQ ? Qh : KhS;
            float ea[5][4];
#pragma unroll
            for (int j = 0; j < 5; j++)
#pragma unroll
                for (int q = 0; q < 4; q++) ea[j][q] = 0.f;
#pragma unroll
            for (int k4 = 0; k4 < 4; k4++) {
                const int kk = k4 * 16 + t4 * 2;
                uint32_t af[4];
                const int r = arow0 + g;
                af[0] = *(const uint32_t*)&Ab[r * STR + kk];
                af[1] = *(const uint32_t*)&Ab[(r + 8) * STR + kk];
                af[2] = *(const uint32_t*)&Ab[r * STR + kk + 8];
                af[3] = *(const uint32_t*)&Ab[(r + 8) * STR + kk + 8];
#pragma unroll
                for (int j = 0; j < 5; j++) {
                    const int n = (nt0 + j) * 8 + g;
                    uint32_t bf2[2];
                    bf2[0] = *(const uint32_t*)&EsS[n * STR + kk];
                    bf2[1] = *(const uint32_t*)&EsS[n * STR + kk + 8];
                    mma_bf16(ea[j], af, bf2);
                }
            }
#pragma unroll
            for (int j = 0; j < 5; j++) {
                const int m = drow0 + g, n = (nt0 + j) * 8 + t4 * 2;
                *(uint32_t*)&S23[m * SSTR + n] = bfpack(ea[j][0], ea[j][1]);
                *(uint32_t*)&S23[(m + 8) * SSTR + n] = bfpack(ea[j][2], ea[j][3]);
            }
        }
        // ---- GEMM2: Q@K^T (split) ----
        float sc[2][4];
#pragma unroll
        for (int j = 0; j < 2; j++)
#pragma unroll
            for (int q = 0; q < 4; q++) sc[j][q] = 0.f;
#pragma unroll
        for (int k4 = 0; k4 < 4; k4++) {
            const int kk = k4 * 16 + t4 * 2;
            uint32_t aH[4], aL[4];
            const int r = sm0 + g;
            aH[0] = *(const uint32_t*)&Qh[r * STR + kk];
            aH[1] = *(const uint32_t*)&Qh[(r + 8) * STR + kk];
            aH[2] = *(const uint32_t*)&Qh[r * STR + kk + 8];
            aH[3] = *(const uint32_t*)&Qh[(r + 8) * STR + kk + 8];
            aL[0] = *(const uint32_t*)&Ql[r * STR + kk];
            aL[1] = *(const uint32_t*)&Ql[(r + 8) * STR + kk];
            aL[2] = *(const uint32_t*)&Ql[r * STR + kk + 8];
            aL[3] = *(const uint32_t*)&Ql[(r + 8) * STR + kk + 8];
#pragma unroll
            for (int j = 0; j < 2; j++) {
                const int n = sn0 + j * 8 + g;
                uint32_t bH2[2], bL2[2];
                bH2[0] = *(const uint32_t*)&KhS[n * STR + kk];
                bH2[1] = *(const uint32_t*)&KhS[n * STR + kk + 8];
                bL2[0] = *(const uint32_t*)&KlS[n * STR + kk];
                bL2[1] = *(const uint32_t*)&KlS[n * STR + kk + 8];
                mma_bf16(sc[j], aH, bH2);
                mma_bf16(sc[j], aH, bL2);
                mma_bf16(sc[j], aL, bH2);
            }
        }
        __syncthreads();

        // ---- logits: gather S23 diagonals + mask ----
#pragma unroll
        for (int j = 0; j < 2; j++) {
            const int ri = sn0 + j * 8 + t4 * 2;
#pragma unroll
            for (int ch = 0; ch < 2; ch++) {
                const int li = sm0 + g + ch * 8;
                const int nn = li - ri + 63;
                float t0 = __bfloat162float(S23[li * SSTR + nn])
                         + __bfloat162float(S23[(64 + ri) * SSTR + nn]);
                float t1 = __bfloat162float(S23[li * SSTR + nn - 1])
                         + __bfloat162float(S23[(65 + ri) * SSTR + nn - 1]);
                float2 lv;
                lv.x = (sc[j][ch * 2 + 0] + t0) * 0.125f + MsS[ri];
                lv.y = (sc[j][ch * 2 + 1] + t1) * 0.125f + MsS[ri + 1];
                *(float2*)&Sl[li * 68 + ri] = lv;
            }
        }
        __syncthreads();

        // ---- online softmax (8 threads/row) ----
        {
            const int row = t >> 3, qq = t & 7;
            float v[8], mx = -1e30f;
#pragma unroll
            for (int c = 0; c < 8; c++) {
                v[c] = Sl[row * 68 + qq * 8 + c];
                mx = fmaxf(mx, v[c]);
            }
            mx = fmaxf(mx, __shfl_xor_sync(0xffffffffu, mx, 1));
            mx = fmaxf(mx, __shfl_xor_sync(0xffffffffu, mx, 2));
            mx = fmaxf(mx, __shfl_xor_sync(0xffffffffu, mx, 4));
            const float mold = Mr[row];
            const float mnew = fmaxf(mold, mx);
            const float corr = __expf(mold - mnew);
            float s = 0.f;
#pragma unroll
            for (int c = 0; c < 8; c++) { v[c] = __expf(v[c] - mnew); s += v[c]; }
            s += __shfl_xor_sync(0xffffffffu, s, 1);
            s += __shfl_xor_sync(0xffffffffu, s, 2);
            s += __shfl_xor_sync(0xffffffffu, s, 4);
            if (qq == 0) { Ls[row] = Ls[row] * corr + s; Mr[row] = mnew; Cs[row] = corr; }
#pragma unroll
            for (int c = 0; c < 8; c += 2) {
                uint32_t hi, lo; bfsplit(v[c], v[c + 1], hi, lo);
                *(uint32_t*)&Ph[row * STR + qq * 8 + c] = hi;
                *(uint32_t*)&Pl[row * STR + qq * 8 + c] = lo;
            }
        }
        __syncthreads();

        // ---- PV (3-term: Ph@Vh + Ph@Vl + Pl@Vh) ----
        {
            const float c0 = Cs[sm0 + g];
            const float c1 = Cs[sm0 + g + 8];
#pragma unroll
            for (int j = 0; j < 2; j++) {
                O[j][0] *= c0; O[j][1] *= c0;
                O[j][2] *= c1; O[j][3] *= c1;
            }
        }
#pragma unroll
        for (int k4 = 0; k4 < 4; k4++) {
            const int kk = k4 * 16 + t4 * 2;
            uint32_t aH[4], aL[4];
            const int r = sm0 + g;
            aH[0] = *(const uint32_t*)&Ph[r * STR + kk];
            aH[1] = *(const uint32_t*)&Ph[(r + 8) * STR + kk];
            aH[2] = *(const uint32_t*)&Ph[r * STR + kk + 8];
            aH[3] = *(const uint32_t*)&Ph[(r + 8) * STR + kk + 8];
            aL[0] = *(const uint32_t*)&Pl[r * STR + kk];
            aL[1] = *(const uint32_t*)&Pl[(r + 8) * STR + kk];
            aL[2] = *(const uint32_t*)&Pl[r * STR + kk + 8];
            aL[3] = *(const uint32_t*)&Pl[(r + 8) * STR + kk + 8];
#pragma unroll
            for (int j = 0; j < 2; j++) {
                const int d = sn0 + j * 8 + g;
                uint32_t bH2[2], bL2[2];
                bH2[0] = *(const uint32_t*)&VhS[d * STR + kk];
                bH2[1] = *(const uint32_t*)&VhS[d * STR + kk + 8];
                bL2[0] = *(const uint32_t*)&VlS[d * STR + kk];
                bL2[1] = *(const uint32_t*)&VlS[d * STR + kk + 8];
                mma_bf16(O[j], aH, bH2);
                mma_bf16(O[j], aH, bL2);
                mma_bf16(O[j], aL, bH2);
            }
        }
    }

    // ---- output [B, Lq, H*64] ----
#pragma unroll
    for (int ch = 0; ch < 2; ch++) {
        const int li = sm0 + g + ch * 8;
        const float inv = 1.0f / Ls[li];
#pragma unroll
        for (int j = 0; j < 2; j++) {
            const int d = sn0 + j * 8 + t4 * 2;
            float2 o;
            o.x = O[j][ch * 2 + 0] * inv;
            o.y = O[j][ch * 2 + 1] * inv;
            *(float2*)(out + ((size_t)(b * LQ) + l0 + li) * DM + hd * 64 + d) = o;
        }
    }
}

// =================================================================================
extern "C" void kernel_launch(void* const* d_in, const int* in_sizes, int n_in,
                              void* d_out, int out_size)
{
    const float* hidden   = (const float*)d_in[0];
    const float* q_hidden = (const float*)d_in[1];
    const float* mask     = (const float*)d_in[2];
    const float* Wq       = (const float*)d_in[3];
    const float* bq       = (const float*)d_in[4];
    const float* Wk       = (const float*)d_in[5];
    const float* bk       = (const float*)d_in[6];
    const float* Wv       = (const float*)d_in[7];
    const float* bv       = (const float*)d_in[8];
    const float* dist     = (const float*)d_in[9];
    float* out = (float*)d_out;

    __nv_bfloat16 *Qh, *Ql, *Kh, *Kl, *VtH, *VtL, *EbH;
    __nv_bfloat16 *Xqh, *Xql, *Xkh, *Xkl, *Wh, *Wl;
    cudaGetSymbolAddress((void**)&Qh,  g_Qh);
    cudaGetSymbolAddress((void**)&Ql,  g_Ql);
    cudaGetSymbolAddress((void**)&Kh,  g_Kh);
    cudaGetSymbolAddress((void**)&Kl,  g_Kl);
    cudaGetSymbolAddress((void**)&VtH, g_VtH);
    cudaGetSymbolAddress((void**)&VtL, g_VtL);
    cudaGetSymbolAddress((void**)&EbH, g_EbH);
    cudaGetSymbolAddress((void**)&Xqh, g_Xqh);
    cudaGetSymbolAddress((void**)&Xql, g_Xql);
    cudaGetSymbolAddress((void**)&Xkh, g_Xkh);
    cudaGetSymbolAddress((void**)&Xkl, g_Xkl);
    cudaGetSymbolAddress((void**)&Wh,  g_Wh);
    cudaGetSymbolAddress((void**)&Wl,  g_Wl);

    cudaFuncSetAttribute(proj_tc, cudaFuncAttributeMaxDynamicSharedMemorySize,
                         PROJ_SMEM_BYTES);
    cudaFuncSetAttribute(attn_tc, cudaFuncAttributeMaxDynamicSharedMemorySize,
                         ATTN_SMEM);

    const int nq = NB * LQ * DM / 4;
    const int nk = NB * LK * DM / 4;
    const int nw = DM * DM / 4;
    const int ne = (2 * MAXPOS - 1) * DHD / 4;
    split_kernel<<<(nq + 255) / 256, 256>>>(q_hidden, Xqh, Xql, nq);
    split_kernel<<<(nk + 255) / 256, 256>>>(hidden,   Xkh, Xkl, nk);
    split_kernel<<<(nw + 255) / 256, 256>>>(Wq, Wh + 0 * (size_t)DM * DM, Wl + 0 * (size_t)DM * DM, nw);
    split_kernel<<<(nw + 255) / 256, 256>>>(Wk, Wh + 1 * (size_t)DM * DM, Wl + 1 * (size_t)DM * DM, nw);
    split_kernel<<<(nw + 255) / 256, 256>>>(Wv, Wh + 2 * (size_t)DM * DM, Wl + 2 * (size_t)DM * DM, nw);
    conv_kernel<<<(ne + 255) / 256, 256>>>(dist, EbH, ne);

    dim3 gq(NB * LQ / 128, DM / 128);
    dim3 gk(NB * LK / 128, DM / 128);
    proj_tc<<<gq, 256, PROJ_SMEM_BYTES>>>(Xqh, Xql,
        Wh + 0 * (size_t)DM * DM, Wl + 0 * (size_t)DM * DM, bq, Qh, Ql, LQ, 0);
    proj_tc<<<gk, 256, PROJ_SMEM_BYTES>>>(Xkh, Xkl,
        Wh + 1 * (size_t)DM * DM, Wl + 1 * (size_t)DM * DM, bk, Kh, Kl, LK, 0);
    proj_tc<<<gk, 256, PROJ_SMEM_BYTES>>>(Xkh, Xkl,
        Wh + 2 * (size_t)DM * DM, Wl + 2 * (size_t)DM * DM, bv, VtH, VtL, LK, 1);

    dim3 ga(LQ / 64, NH, NB);
    attn_tc<<<ga, 512, ATTN_SMEM>>>(mask, out);
}

// round 9
// speedup vs baseline: 1.6774x; 1.6774x over previous
#include <cuda_runtime.h>
#include <cuda_fp16.h>
#include <math.h>
#include <stdint.h>
#include <string.h>

#define NH   16
#define DHD  64
#define NB   4
#define LQ   1024
#define LK   2048
#define DM   1024
#define MAXPOS 2048
#define STR  72    // fp16 smem row stride (144B)
#define SSTR 136   // S23 fp16 stride

// ---------------- static device scratch ----------------
__device__ __half g_Q[(size_t)NB*NH*LQ*DHD];
__device__ __half g_K[(size_t)NB*NH*LK*DHD];
__device__ __half g_Vt[(size_t)NB*NH*DHD*LK];   // [b,h][d][r]
__device__ __half g_E[(size_t)(2*MAXPOS-1)*DHD];

__device__ __half g_Xq[(size_t)NB*LQ*DM];
__device__ __half g_Xk[(size_t)NB*LK*DM];
__device__ __half g_W[3][(size_t)DM*DM];

// ============================ helpers ============================
__device__ __forceinline__ uint32_t smem_u32(const void* p) {
    uint32_t a;
    asm("{ .reg .u64 t; cvta.to.shared.u64 t, %1; cvt.u32.u64 %0, t; }"
        : "=r"(a) : "l"(p));
    return a;
}
__device__ __forceinline__ void cp_async16(uint32_t saddr, const void* gaddr) {
    asm volatile("cp.async.cg.shared.global [%0], [%1], 16;" :: "r"(saddr), "l"(gaddr));
}
__device__ __forceinline__ void cp_commit() { asm volatile("cp.async.commit_group;"); }
template <int N>
__device__ __forceinline__ void cp_wait() { asm volatile("cp.async.wait_group %0;" :: "n"(N)); }

// fp16 m16n8k16 MMA, fp32 accumulate (sm_80+, legal in compute_103)
__device__ __forceinline__ void mma_f16(float* c, const uint32_t* a, const uint32_t* b) {
    asm volatile(
        "mma.sync.aligned.m16n8k16.row.col.f32.f16.f16.f32 "
        "{%0,%1,%2,%3}, {%4,%5,%6,%7}, {%8,%9}, {%0,%1,%2,%3};"
        : "+f"(c[0]), "+f"(c[1]), "+f"(c[2]), "+f"(c[3])
        : "r"(a[0]), "r"(a[1]), "r"(a[2]), "r"(a[3]), "r"(b[0]), "r"(b[1]));
}
__device__ __forceinline__ uint32_t hpack(float x, float y) {
    __half2 h = __floats2half2_rn(x, y);
    uint32_t u; memcpy(&u, &h, 4); return u;
}

// =================================================================================
// fp32 -> fp16 conversion
// =================================================================================
__global__ void convh_kernel(const float* __restrict__ x,
                             __half* __restrict__ y, int n4)
{
    int i = blockIdx.x * blockDim.x + threadIdx.x;
    if (i >= n4) return;
    float4 v = ((const float4*)x)[i];
    ((uint32_t*)y)[2*i]   = hpack(v.x, v.y);
    ((uint32_t*)y)[2*i+1] = hpack(v.z, v.w);
}

// =================================================================================
// Projection GEMM, fp16 single-pass: out[m,n] = X[m,:]@W[n,:] + bias[n]
// Block 128x128x32, 8 warps, cp.async double buffer.
// mode 0: out fp16 [B,H,L,64]; mode 1: V^T fp16 [B,H,64,LK]
// =================================================================================
#define BK      32
#define KS_STR  40
#define TILE_HF (128 * KS_STR)
#define STAGE_HF (2 * TILE_HF)
#define PROJ_SMEM_BYTES (2 * STAGE_HF * 2)   // 40960 B

__global__ __launch_bounds__(256)
void proj_tc(const __half* __restrict__ A_g, const __half* __restrict__ B_g,
             const float* __restrict__ bias,
             __half* __restrict__ outH, int L, int mode)
{
    extern __shared__ __half smem[];
    const uint32_t smem_b = smem_u32(smem);
    const int t = threadIdx.x, lane = t & 31;
    const int wid = t >> 5, g = lane >> 2, t4 = lane & 3;
    const int wm0 = (wid & 3) * 32, wn0 = (wid >> 2) * 64;
    const int m0 = blockIdx.x * 128, n0 = blockIdx.y * 128;
    const int c0 = t * 2;
    const int row0 = c0 >> 2, seg0 = c0 & 3;
    const int row1 = (c0 + 1) >> 2, seg1 = (c0 + 1) & 3;
    const int NS = DM / BK;

    auto load_stage = [&](int kc) {
        const int k0 = kc * BK;
        const uint32_t sb = smem_b + (uint32_t)(kc & 1) * STAGE_HF * 2;
        const uint32_t so0 = (uint32_t)(row0 * KS_STR + seg0 * 8) * 2;
        const uint32_t so1 = (uint32_t)(row1 * KS_STR + seg1 * 8) * 2;
        cp_async16(sb + so0, A_g + (size_t)(m0 + row0) * DM + k0 + seg0 * 8);
        cp_async16(sb + so1, A_g + (size_t)(m0 + row1) * DM + k0 + seg1 * 8);
        cp_async16(sb + TILE_HF * 2 + so0, B_g + (size_t)(n0 + row0) * DM + k0 + seg0 * 8);
        cp_async16(sb + TILE_HF * 2 + so1, B_g + (size_t)(n0 + row1) * DM + k0 + seg1 * 8);
        cp_commit();
    };

    float acc[2][8][4];
#pragma unroll
    for (int i = 0; i < 2; i++)
#pragma unroll
        for (int j = 0; j < 8; j++)
#pragma unroll
            for (int q = 0; q < 4; q++) acc[i][j][q] = 0.0f;

    load_stage(0);
    for (int kc = 0; kc < NS; kc++) {
        if (kc + 1 < NS) { load_stage(kc + 1); cp_wait<1>(); }
        else             { cp_wait<0>(); }
        __syncthreads();
        const __half* sA = smem + (size_t)(kc & 1) * STAGE_HF;
        const __half* sB = sA + TILE_HF;
#pragma unroll
        for (int ks = 0; ks < BK; ks += 16) {
            uint32_t aF[2][4], bF[8][2];
            const int kk = ks + t4 * 2;
#pragma unroll
            for (int i = 0; i < 2; i++) {
                const int r = wm0 + i * 16 + g;
                aF[i][0] = *(const uint32_t*)&sA[r * KS_STR + kk];
                aF[i][1] = *(const uint32_t*)&sA[(r + 8) * KS_STR + kk];
                aF[i][2] = *(const uint32_t*)&sA[r * KS_STR + kk + 8];
                aF[i][3] = *(const uint32_t*)&sA[(r + 8) * KS_STR + kk + 8];
            }
#pragma unroll
            for (int j = 0; j < 8; j++) {
                const int n = wn0 + j * 8 + g;
                bF[j][0] = *(const uint32_t*)&sB[n * KS_STR + kk];
                bF[j][1] = *(const uint32_t*)&sB[n * KS_STR + kk + 8];
            }
#pragma unroll
            for (int i = 0; i < 2; i++)
#pragma unroll
                for (int j = 0; j < 8; j++)
                    mma_f16(acc[i][j], aF[i], bF[j]);
        }
        __syncthreads();
    }
#pragma unroll
    for (int i = 0; i < 2; i++)
#pragma unroll
        for (int j = 0; j < 8; j++) {
            const int cc = n0 + wn0 + j * 8 + t4 * 2;
            const int hh = cc >> 6, dh = cc & 63;
            const float b0 = __ldg(&bias[cc]), b1 = __ldg(&bias[cc + 1]);
#pragma unroll
            for (int rr = 0; rr < 2; rr++) {
                const int r = m0 + wm0 + i * 16 + g + rr * 8;
                const int bidx = r / L, l = r - bidx * L;
                const float f0 = acc[i][j][rr * 2 + 0] + b0;
                const float f1 = acc[i][j][rr * 2 + 1] + b1;
                if (mode == 0) {
                    const size_t base = ((size_t)(bidx * NH + hh) * L + l) * DHD + dh;
                    *(__half2*)&outH[base] = __floats2half2_rn(f0, f1);
                } else {
                    const size_t base = ((size_t)(bidx * NH + hh) * DHD + dh) * LK + l;
                    outH[base] = __float2half(f0);
                    outH[base + LK] = __float2half(f1);
                }
            }
        }
}

// =================================================================================
// Tensor-core attention, fp16 single-pass: 512 threads, banded GEMM1, double-buffered
// =================================================================================
#define OFF_KH  0
#define OFF_VTH 9216
#define OFF_ES  18432
#define OFF_MS  36864
#define BUF_BYTES 37120

#define SM_S23 0
#define SM_SL  34816
#define SM_QH  52224
#define SM_BUF 61440
#define SM_PH  135680
#define SM_MR  144896
#define SM_LS  145152
#define SM_CS  145408
#define ATTN_SMEM 145664

__global__ __launch_bounds__(512, 1)
void attn_tc(const float* __restrict__ mask, float* __restrict__ out)
{
    extern __shared__ char smc[];
    const uint32_t sbu = smem_u32(smc);
    __half* S23 = (__half*)(smc + SM_S23);    // [128][SSTR]
    float* Sl = (float*)(smc + SM_SL);        // [64][68]
    __half* Qh = (__half*)(smc + SM_QH);
    __half* Ph = (__half*)(smc + SM_PH);
    float* Mr = (float*)(smc + SM_MR);
    float* Ls = (float*)(smc + SM_LS);
    float* Cs = (float*)(smc + SM_CS);

    const int t = threadIdx.x, lane = t & 31, w = t >> 5;   // 16 warps
    const int g = lane >> 2, t4 = lane & 3;
    const int sm0 = (w & 3) * 16, sn0 = (w >> 2) * 16;      // QK/PV: 4m x 4n of 16x16
    const int l0 = blockIdx.x * 64, hd = blockIdx.y, b = blockIdx.z;

    const __half* Qg = g_Q + ((size_t)(b * NH + hd) * LQ + l0) * DHD;
    const __half* Kg = g_K + (size_t)(b * NH + hd) * LK * DHD;
    const __half* Vg = g_Vt + (size_t)(b * NH + hd) * DHD * LK;
    const float* mg = mask + (size_t)b * LK;

    // initial loads: Q + first buffer (one cp group)
    {
        const int row = t >> 3, c = t & 7;
        cp_async16(sbu + SM_QH + row * 144 + c * 16, Qg + row * DHD + c * 8);
        cp_async16(sbu + SM_BUF + OFF_KH + row * 144 + c * 16, Kg + (size_t)row * DHD + c * 8);
        cp_async16(sbu + SM_BUF + OFF_VTH + row * 144 + c * 16, Vg + (size_t)row * LK + c * 8);
        const int eb0 = l0 + (MAXPOS - 64);
#pragma unroll
        for (int i = 0; i < 2; i++) {
            int q = t + 512 * i;
            if (q < 127 * 8) {
                int rw = q >> 3, cc = q & 7;
                cp_async16(sbu + SM_BUF + OFF_ES + rw * 144 + cc * 16,
                           g_E + (size_t)(eb0 + rw) * DHD + cc * 8);
            }
        }
        if (t < 16) cp_async16(sbu + SM_BUF + OFF_MS + t * 16, mg + t * 4);
        cp_commit();
    }

    if (t < 64) { Mr[t] = -1e30f; Ls[t] = 0.f; }
    if (t < 72) {  // zero Es row 127 in both buffers
        int bb = t / 36, wd = t % 36;
        *(uint32_t*)(smc + SM_BUF + bb * BUF_BYTES + OFF_ES + 127 * 144 + wd * 4) = 0u;
    }

    float O[2][4];
#pragma unroll
    for (int j = 0; j < 2; j++)
#pragma unroll
        for (int q = 0; q < 4; q++) O[j][q] = 0.f;

    // GEMM1 banding: 16-row m-blocks, 80-wide diagonal band (10 n-tiles, 5/warp-half)
    const int rb16 = w >> 1;
    int arow0, band0, drow0;
    bool isQ = (rb16 < 4);
    if (isQ) { arow0 = rb16 * 16; band0 = rb16 * 16; drow0 = rb16 * 16; }
    else     { int rk = (rb16 - 4) * 16; arow0 = rk; band0 = 48 - rk; drow0 = 64 + rk; }
    const int nt0 = band0 / 8 + (w & 1) * 5;

    for (int kt = 0; kt < LK / 64; kt++) {
        const int bb = kt & 1;
        const char* B = smc + SM_BUF + bb * BUF_BYTES;
        cp_wait<0>();
        __syncthreads();

        if (kt + 1 < LK / 64) {  // prefetch next tiles
            const int r1 = (kt + 1) * 64;
            const uint32_t P = sbu + SM_BUF + (bb ^ 1) * BUF_BYTES;
            const int row = t >> 3, c = t & 7;
            cp_async16(P + OFF_KH + row * 144 + c * 16, Kg + (size_t)(r1 + row) * DHD + c * 8);
            cp_async16(P + OFF_VTH + row * 144 + c * 16, Vg + (size_t)row * LK + r1 + c * 8);
            const int eb1 = l0 - r1 + (MAXPOS - 64);
#pragma unroll
            for (int i = 0; i < 2; i++) {
                int q = t + 512 * i;
                if (q < 127 * 8) {
                    int rw = q >> 3, cc = q & 7;
                    cp_async16(P + OFF_ES + rw * 144 + cc * 16,
                               g_E + (size_t)(eb1 + rw) * DHD + cc * 8);
                }
            }
            if (t < 16) cp_async16(P + OFF_MS + t * 16, mg + r1 + t * 4);
            cp_commit();
        }

        const __half* KhS = (const __half*)(B + OFF_KH);
        const __half* VhS = (const __half*)(B + OFF_VTH);
        const __half* EsS = (const __half*)(B + OFF_ES);
        const float* MsS = (const float*)(B + OFF_MS);

        // ---- GEMM1 (banded): S23 = [Q;K] @ E^T ----
        {
            const __half* Ab = isQ ? Qh : KhS;
            float ea[5][4];
#pragma unroll
            for (int j = 0; j < 5; j++)
#pragma unroll
                for (int q = 0; q < 4; q++) ea[j][q] = 0.f;
#pragma unroll
            for (int k4 = 0; k4 < 4; k4++) {
                const int kk = k4 * 16 + t4 * 2;
                uint32_t af[4];
                const int r = arow0 + g;
                af[0] = *(const uint32_t*)&Ab[r * STR + kk];
                af[1] = *(const uint32_t*)&Ab[(r + 8) * STR + kk];
                af[2] = *(const uint32_t*)&Ab[r * STR + kk + 8];
                af[3] = *(const uint32_t*)&Ab[(r + 8) * STR + kk + 8];
#pragma unroll
                for (int j = 0; j < 5; j++) {
                    const int n = (nt0 + j) * 8 + g;
                    uint32_t bf2[2];
                    bf2[0] = *(const uint32_t*)&EsS[n * STR + kk];
                    bf2[1] = *(const uint32_t*)&EsS[n * STR + kk + 8];
                    mma_f16(ea[j], af, bf2);
                }
            }
#pragma unroll
            for (int j = 0; j < 5; j++) {
                const int m = drow0 + g, n = (nt0 + j) * 8 + t4 * 2;
                *(uint32_t*)&S23[m * SSTR + n] = hpack(ea[j][0], ea[j][1]);
                *(uint32_t*)&S23[(m + 8) * SSTR + n] = hpack(ea[j][2], ea[j][3]);
            }
        }
        // ---- GEMM2: Q@K^T ----
        float sc[2][4];
#pragma unroll
        for (int j = 0; j < 2; j++)
#pragma unroll
            for (int q = 0; q < 4; q++) sc[j][q] = 0.f;
#pragma unroll
        for (int k4 = 0; k4 < 4; k4++) {
            const int kk = k4 * 16 + t4 * 2;
            uint32_t aF[4];
            const int r = sm0 + g;
            aF[0] = *(const uint32_t*)&Qh[r * STR + kk];
            aF[1] = *(const uint32_t*)&Qh[(r + 8) * STR + kk];
            aF[2] = *(const uint32_t*)&Qh[r * STR + kk + 8];
            aF[3] = *(const uint32_t*)&Qh[(r + 8) * STR + kk + 8];
#pragma unroll
            for (int j = 0; j < 2; j++) {
                const int n = sn0 + j * 8 + g;
                uint32_t bF[2];
                bF[0] = *(const uint32_t*)&KhS[n * STR + kk];
                bF[1] = *(const uint32_t*)&KhS[n * STR + kk + 8];
                mma_f16(sc[j], aF, bF);
            }
        }
        __syncthreads();

        // ---- logits: gather S23 diagonals + mask ----
#pragma unroll
        for (int j = 0; j < 2; j++) {
            const int ri = sn0 + j * 8 + t4 * 2;
#pragma unroll
            for (int ch = 0; ch < 2; ch++) {
                const int li = sm0 + g + ch * 8;
                const int nn = li - ri + 63;
                float t0 = __half2float(S23[li * SSTR + nn])
                         + __half2float(S23[(64 + ri) * SSTR + nn]);
                float t1 = __half2float(S23[li * SSTR + nn - 1])
                         + __half2float(S23[(65 + ri) * SSTR + nn - 1]);
                float2 lv;
                lv.x = (sc[j][ch * 2 + 0] + t0) * 0.125f + MsS[ri];
                lv.y = (sc[j][ch * 2 + 1] + t1) * 0.125f + MsS[ri + 1];
                *(float2*)&Sl[li * 68 + ri] = lv;
            }
        }
        __syncthreads();

        // ---- online softmax (8 threads/row) ----
        {
            const int row = t >> 3, qq = t & 7;
            float v[8], mx = -1e30f;
#pragma unroll
            for (int c = 0; c < 8; c++) {
                v[c] = Sl[row * 68 + qq * 8 + c];
                mx = fmaxf(mx, v[c]);
            }
            mx = fmaxf(mx, __shfl_xor_sync(0xffffffffu, mx, 1));
            mx = fmaxf(mx, __shfl_xor_sync(0xffffffffu, mx, 2));
            mx = fmaxf(mx, __shfl_xor_sync(0xffffffffu, mx, 4));
            const float mold = Mr[row];
            const float mnew = fmaxf(mold, mx);
            const float corr = __expf(mold - mnew);
            float s = 0.f;
#pragma unroll
            for (int c = 0; c < 8; c++) { v[c] = __expf(v[c] - mnew); s += v[c]; }
            s += __shfl_xor_sync(0xffffffffu, s, 1);
            s += __shfl_xor_sync(0xffffffffu, s, 2);
            s += __shfl_xor_sync(0xffffffffu, s, 4);
            if (qq == 0) { Ls[row] = Ls[row] * corr + s; Mr[row] = mnew; Cs[row] = corr; }
#pragma unroll
            for (int c = 0; c < 8; c += 2)
                *(uint32_t*)&Ph[row * STR + qq * 8 + c] = hpack(v[c], v[c + 1]);
        }
        __syncthreads();

        // ---- PV ----
        {
            const float c0 = Cs[sm0 + g];
            const float c1 = Cs[sm0 + g + 8];
#pragma unroll
            for (int j = 0; j < 2; j++) {
                O[j][0] *= c0; O[j][1] *= c0;
                O[j][2] *= c1; O[j][3] *= c1;
            }
        }
#pragma unroll
        for (int k4 = 0; k4 < 4; k4++) {
            const int kk = k4 * 16 + t4 * 2;
            uint32_t aF[4];
            const int r = sm0 + g;
            aF[0] = *(const uint32_t*)&Ph[r * STR + kk];
            aF[1] = *(const uint32_t*)&Ph[(r + 8) * STR + kk];
            aF[2] = *(const uint32_t*)&Ph[r * STR + kk + 8];
            aF[3] = *(const uint32_t*)&Ph[(r + 8) * STR + kk + 8];
#pragma unroll
            for (int j = 0; j < 2; j++) {
                const int d = sn0 + j * 8 + g;
                uint32_t bF[2];
                bF[0] = *(const uint32_t*)&VhS[d * STR + kk];
                bF[1] = *(const uint32_t*)&VhS[d * STR + kk + 8];
                mma_f16(O[j], aF, bF);
            }
        }
    }

    // ---- output [B, Lq, H*64] ----
#pragma unroll
    for (int ch = 0; ch < 2; ch++) {
        const int li = sm0 + g + ch * 8;
        const float inv = 1.0f / Ls[li];
#pragma unroll
        for (int j = 0; j < 2; j++) {
            const int d = sn0 + j * 8 + t4 * 2;
            float2 o;
            o.x = O[j][ch * 2 + 0] * inv;
            o.y = O[j][ch * 2 + 1] * inv;
            *(float2*)(out + ((size_t)(b * LQ) + l0 + li) * DM + hd * 64 + d) = o;
        }
    }
}

// =================================================================================
extern "C" void kernel_launch(void* const* d_in, const int* in_sizes, int n_in,
                              void* d_out, int out_size)
{
    const float* hidden   = (const float*)d_in[0];
    const float* q_hidden = (const float*)d_in[1];
    const float* mask     = (const float*)d_in[2];
    const float* Wq       = (const float*)d_in[3];
    const float* bq       = (const float*)d_in[4];
    const float* Wk       = (const float*)d_in[5];
    const float* bk       = (const float*)d_in[6];
    const float* Wv       = (const float*)d_in[7];
    const float* bv       = (const float*)d_in[8];
    const float* dist     = (const float*)d_in[9];
    float* out = (float*)d_out;

    __half *Qp, *Kp, *Vtp, *Ep, *Xq, *Xk, *Wp;
    cudaGetSymbolAddress((void**)&Qp,  g_Q);
    cudaGetSymbolAddress((void**)&Kp,  g_K);
    cudaGetSymbolAddress((void**)&Vtp, g_Vt);
    cudaGetSymbolAddress((void**)&Ep,  g_E);
    cudaGetSymbolAddress((void**)&Xq,  g_Xq);
    cudaGetSymbolAddress((void**)&Xk,  g_Xk);
    cudaGetSymbolAddress((void**)&Wp,  g_W);

    cudaFuncSetAttribute(proj_tc, cudaFuncAttributeMaxDynamicSharedMemorySize,
                         PROJ_SMEM_BYTES);
    cudaFuncSetAttribute(attn_tc, cudaFuncAttributeMaxDynamicSharedMemorySize,
                         ATTN_SMEM);

    const int nq = NB * LQ * DM / 4;
    const int nk = NB * LK * DM / 4;
    const int nw = DM * DM / 4;
    const int ne = (2 * MAXPOS - 1) * DHD / 4;
    convh_kernel<<<(nq + 255) / 256, 256>>>(q_hidden, Xq, nq);
    convh_kernel<<<(nk + 255) / 256, 256>>>(hidden,   Xk, nk);
    convh_kernel<<<(nw + 255) / 256, 256>>>(Wq, Wp + 0 * (size_t)DM * DM, nw);
    convh_kernel<<<(nw + 255) / 256, 256>>>(Wk, Wp + 1 * (size_t)DM * DM, nw);
    convh_kernel<<<(nw + 255) / 256, 256>>>(Wv, Wp + 2 * (size_t)DM * DM, nw);
    convh_kernel<<<(ne + 255) / 256, 256>>>(dist, Ep, ne);

    dim3 gq(NB * LQ / 128, DM / 128);
    dim3 gk(NB * LK / 128, DM / 128);
    proj_tc<<<gq, 256, PROJ_SMEM_BYTES>>>(Xq, Wp + 0 * (size_t)DM * DM, bq, Qp,  LQ, 0);
    proj_tc<<<gk, 256, PROJ_SMEM_BYTES>>>(Xk, Wp + 1 * (size_t)DM * DM, bk, Kp,  LK, 0);
    proj_tc<<<gk, 256, PROJ_SMEM_BYTES>>>(Xk, Wp + 2 * (size_t)DM * DM, bv, Vtp, LK, 1);

    dim3 ga(LQ / 64, NH, NB);
    attn_tc<<<ga, 512, ATTN_SMEM>>>(mask, out);
}